// round 16
// baseline (speedup 1.0000x reference)
#include <cuda_runtime.h>
#include <cuda_fp16.h>
#include <cstdint>
#include <cstddef>

// Problem constants: N=100000, D_IN=D_OUT=256, E=3.2M
#define MAXN 100352
#define MAXE 3200000
#define D    256

// Scratch (device globals; allocation is forbidden)
__device__ __align__(16) __half g_h2[(size_t)MAXN * D];  // drs[j] * (x@W^T)[j], fp16
__device__ __align__(16) __half g_xh[(size_t)MAXN * D];  // fp16(x); rows >= N stay zero
__device__ __align__(16) __half g_wh[D * D];             // fp16(W)
__device__ float g_drs[MAXN];
__device__ int   g_cnt8[8 * MAXN];   // 8-way split histogram (contention /8)
__device__ int   g_cnt[MAXN];        // merged degree (written by drs_compute)
__device__ int   g_excl[MAXN];
__device__ int   g_blksum[512];
__device__ int   g_rowptr[MAXN + 1];
__device__ int   g_off[MAXN];
__device__ int   g_col[MAXE];

__device__ __forceinline__ uint32_t smem_u32(const void* p) {
    return (uint32_t)__cvta_generic_to_shared(p);
}

__device__ __forceinline__ void cp_cg16(uint32_t dst, const void* src) {
    asm volatile("cp.async.cg.shared.global [%0], [%1], 16;" :: "r"(dst), "l"(src));
}

template<int NPend>
__device__ __forceinline__ void cp_wait() {
    asm volatile("cp.async.wait_group %0;" :: "n"(NPend) : "memory");
}

// ---------------------------------------------------------------------------
// fp32 -> fp16 bulk convert (8 floats / thread)
// ---------------------------------------------------------------------------
__global__ void cvt_f2h(const float* __restrict__ in, __half* __restrict__ out, int n8) {
    int i = blockIdx.x * blockDim.x + threadIdx.x;
    if (i >= n8) return;
    float4 a = reinterpret_cast<const float4*>(in)[2 * i];
    float4 b = reinterpret_cast<const float4*>(in)[2 * i + 1];
    __half2 h[4];
    h[0] = __floats2half2_rn(a.x, a.y);
    h[1] = __floats2half2_rn(a.z, a.w);
    h[2] = __floats2half2_rn(b.x, b.y);
    h[3] = __floats2half2_rn(b.z, b.w);
    reinterpret_cast<uint4*>(out)[i] = *reinterpret_cast<uint4*>(h);
}

// ---------------------------------------------------------------------------
// Degree histogram, 8-way split: per-address contention drops 32 -> 4.
// ---------------------------------------------------------------------------
__global__ void cnt_edges8(const int* __restrict__ src, int E) {
    int e = blockIdx.x * blockDim.x + threadIdx.x;
    if (e < E) {
        int b = e & 7;
        atomicAdd(&g_cnt8[b * MAXN + src[e]], 1);
    }
}

// drs = rsqrt(deg+1); also writes merged g_cnt for the scan.
__global__ void drs_compute(int N) {
    int i = blockIdx.x * blockDim.x + threadIdx.x;
    if (i < N) {
        int c = 0;
#pragma unroll
        for (int b = 0; b < 8; b++) c += g_cnt8[b * MAXN + i];
        g_cnt[i] = c;
        g_drs[i] = rsqrtf((float)c + 1.0f);
    }
}

// ---------------------------------------------------------------------------
// Prefix sum over g_cnt -> g_rowptr
// ---------------------------------------------------------------------------
__global__ void scan_phase1(int N) {
    __shared__ int sh[256];
    int i = blockIdx.x * 256 + threadIdx.x;
    int v = (i < N) ? g_cnt[i] : 0;
    sh[threadIdx.x] = v;
    __syncthreads();
#pragma unroll
    for (int off = 1; off < 256; off <<= 1) {
        int t = (threadIdx.x >= off) ? sh[threadIdx.x - off] : 0;
        __syncthreads();
        sh[threadIdx.x] += t;
        __syncthreads();
    }
    if (i < N) g_excl[i] = sh[threadIdx.x] - v;
    if (threadIdx.x == 255) g_blksum[blockIdx.x] = sh[255];
}

__global__ void scan_phase2(int nb) {
    __shared__ int sh[512];
    int t = threadIdx.x;
    int v = (t < nb) ? g_blksum[t] : 0;
    sh[t] = v;
    __syncthreads();
#pragma unroll
    for (int off = 1; off < 512; off <<= 1) {
        int u = (t >= off) ? sh[t - off] : 0;
        __syncthreads();
        sh[t] += u;
        __syncthreads();
    }
    if (t < nb) g_blksum[t] = sh[t] - v;
}

__global__ void scan_phase3(int N, int E) {
    int i = blockIdx.x * 256 + threadIdx.x;
    if (i < N) {
        int r = g_excl[i] + g_blksum[blockIdx.x];
        g_rowptr[i] = r;
        g_off[i] = r;
    }
    if (i == 0) g_rowptr[N] = E;
}

__global__ void build_col(const int* __restrict__ src, const int* __restrict__ dst, int E) {
    int e = blockIdx.x * blockDim.x + threadIdx.x;
    if (e < E) {
        int p = atomicAdd(&g_off[src[e]], 1);
        g_col[p] = dst[e];
    }
}

// ---------------------------------------------------------------------------
// cp.async 3-stage pipelined HGEMM (fp16 in, fp32 acc):
//   g_h2 = fp16( drs[i] * (xh @ wh^T) )
// 128x128 block tile, BK=32, 8 warps (2x4 layout), 80B smem row stride.
// B fragments loaded via paired ldmatrix.x4 (2 per k-step instead of 4 x2).
// ---------------------------------------------------------------------------
#define BK      32
#define STRIDE  40
#define TILEH   (128 * STRIDE)
#define STAGES  3

__global__ void __launch_bounds__(256, 2) hgemm16(const __half* __restrict__ Ah,
                                                  const __half* __restrict__ Bh,
                                                  int M) {
    extern __shared__ __half smemraw[];

    const int tid  = threadIdx.x;
    const int lane = tid & 31;
    const int wid  = tid >> 5;
    const int wm   = wid >> 2;
    const int wn   = wid & 3;
    const int brow = blockIdx.y * 128;
    const int bcol = blockIdx.x * 128;

    float acc[4][4][4];
#pragma unroll
    for (int mt = 0; mt < 4; mt++)
#pragma unroll
        for (int nt = 0; nt < 4; nt++)
#pragma unroll
            for (int q = 0; q < 4; q++) acc[mt][nt][q] = 0.0f;

    const int c0r = (tid)       >> 2, c0s = ((tid)       & 3) * 8;
    const int c1r = (tid + 256) >> 2, c1s = ((tid + 256) & 3) * 8;

    auto load_stage = [&](int st, int k0) {
        __half* As = smemraw + st * 2 * TILEH;
        __half* Bs = As + TILEH;
        cp_cg16(smem_u32(As + c0r * STRIDE + c0s), Ah + (size_t)(brow + c0r) * 256 + k0 + c0s);
        cp_cg16(smem_u32(Bs + c0r * STRIDE + c0s), Bh + (size_t)(bcol + c0r) * 256 + k0 + c0s);
        cp_cg16(smem_u32(As + c1r * STRIDE + c1s), Ah + (size_t)(brow + c1r) * 256 + k0 + c1s);
        cp_cg16(smem_u32(Bs + c1r * STRIDE + c1s), Bh + (size_t)(bcol + c1r) * 256 + k0 + c1s);
        asm volatile("cp.async.commit_group;" ::: "memory");
    };

    auto compute_stage = [&](int st) {
        __half* As = smemraw + st * 2 * TILEH;
        __half* Bs = As + TILEH;
#pragma unroll
        for (int ks = 0; ks < 2; ks++) {
            uint32_t a[4][4], b[4][2];
#pragma unroll
            for (int mt = 0; mt < 4; mt++) {
                uint32_t addr = smem_u32(As + (wm * 64 + mt * 16 + (lane & 15)) * STRIDE
                                            + ks * 16 + (lane >> 4) * 8);
                asm volatile("ldmatrix.sync.aligned.m8n8.x4.shared.b16 {%0,%1,%2,%3}, [%4];"
                             : "=r"(a[mt][0]), "=r"(a[mt][1]), "=r"(a[mt][2]), "=r"(a[mt][3])
                             : "r"(addr));
            }
            // B: two x4 loads, each covering an adjacent n-tile pair.
#pragma unroll
            for (int ntp = 0; ntp < 2; ntp++) {
                int row = wn * 32 + ntp * 16 + (lane >> 4) * 8 + (lane & 7);
                int kof = ks * 16 + ((lane >> 3) & 1) * 8;
                uint32_t addr = smem_u32(Bs + row * STRIDE + kof);
                asm volatile("ldmatrix.sync.aligned.m8n8.x4.shared.b16 {%0,%1,%2,%3}, [%4];"
                             : "=r"(b[2*ntp][0]), "=r"(b[2*ntp][1]),
                               "=r"(b[2*ntp+1][0]), "=r"(b[2*ntp+1][1])
                             : "r"(addr));
            }
#pragma unroll
            for (int mt = 0; mt < 4; mt++)
#pragma unroll
                for (int nt = 0; nt < 4; nt++)
                    asm volatile(
                        "mma.sync.aligned.m16n8k16.row.col.f32.f16.f16.f32 "
                        "{%0,%1,%2,%3},{%4,%5,%6,%7},{%8,%9},{%0,%1,%2,%3};"
                        : "+f"(acc[mt][nt][0]), "+f"(acc[mt][nt][1]),
                          "+f"(acc[mt][nt][2]), "+f"(acc[mt][nt][3])
                        : "r"(a[mt][0]), "r"(a[mt][1]), "r"(a[mt][2]), "r"(a[mt][3]),
                          "r"(b[nt][0]), "r"(b[nt][1]));
        }
    };

    load_stage(0, 0);
    load_stage(1, BK);

#pragma unroll
    for (int it = 0; it < 8; it++) {
        if (it + 2 < 8) load_stage((it + 2) % STAGES, (it + 2) * BK);
        if (it < 6)      cp_wait<2>();
        else if (it == 6) cp_wait<1>();
        else              cp_wait<0>();
        __syncthreads();
        compute_stage(it % STAGES);
        __syncthreads();
    }

    const int tg = lane >> 2, tq = lane & 3;
#pragma unroll
    for (int mt = 0; mt < 4; mt++) {
        int r0 = brow + wm * 64 + mt * 16 + tg;
        int r1 = r0 + 8;
        float s0 = (r0 < M) ? g_drs[r0] : 0.f;
        float s1 = (r1 < M) ? g_drs[r1] : 0.f;
#pragma unroll
        for (int nt = 0; nt < 4; nt++) {
            int c = bcol + wn * 32 + nt * 8 + tq * 2;
            if (r0 < M)
                *reinterpret_cast<__half2*>(g_h2 + (size_t)r0 * D + c) =
                    __floats2half2_rn(acc[mt][nt][0] * s0, acc[mt][nt][1] * s0);
            if (r1 < M)
                *reinterpret_cast<__half2*>(g_h2 + (size_t)r1 * D + c) =
                    __floats2half2_rn(acc[mt][nt][2] * s1, acc[mt][nt][3] * s1);
        }
    }
}

// ---------------------------------------------------------------------------
// Aggregation: one warp per node, 4-way unrolled gather (h2 prescaled by drs).
// out[i] = drs[i] * ( h2[i] + sum_{j in adj(i)} h2[j] )
// ---------------------------------------------------------------------------
__global__ void __launch_bounds__(256) aggregate(float* __restrict__ out, int N) {
    int warp = (blockIdx.x * blockDim.x + threadIdx.x) >> 5;
    int lane = threadIdx.x & 31;
    if (warp >= N) return;
    const int i = warp;

    float acc[8];
    {
        uint4 w = *reinterpret_cast<const uint4*>(g_h2 + (size_t)i * D + lane * 8);
        const __half2* hv = reinterpret_cast<const __half2*>(&w);
#pragma unroll
        for (int q = 0; q < 4; q++) {
            float2 f = __half22float2(hv[q]);
            acc[2*q + 0] = f.x;
            acc[2*q + 1] = f.y;
        }
    }

    int s = g_rowptr[i];
    int e = g_rowptr[i + 1];
    for (int b = s; b < e; b += 32) {
        int nidx = (b + lane < e) ? __ldcs(&g_col[b + lane]) : 0;
        int cnt = min(32, e - b);
        int t = 0;
        for (; t + 4 <= cnt; t += 4) {
            int j0 = __shfl_sync(0xffffffffu, nidx, t + 0);
            int j1 = __shfl_sync(0xffffffffu, nidx, t + 1);
            int j2 = __shfl_sync(0xffffffffu, nidx, t + 2);
            int j3 = __shfl_sync(0xffffffffu, nidx, t + 3);
            uint4 w0 = *reinterpret_cast<const uint4*>(g_h2 + (size_t)j0 * D + lane * 8);
            uint4 w1 = *reinterpret_cast<const uint4*>(g_h2 + (size_t)j1 * D + lane * 8);
            uint4 w2 = *reinterpret_cast<const uint4*>(g_h2 + (size_t)j2 * D + lane * 8);
            uint4 w3 = *reinterpret_cast<const uint4*>(g_h2 + (size_t)j3 * D + lane * 8);
            const __half2* h0 = reinterpret_cast<const __half2*>(&w0);
            const __half2* h1 = reinterpret_cast<const __half2*>(&w1);
            const __half2* h2 = reinterpret_cast<const __half2*>(&w2);
            const __half2* h3 = reinterpret_cast<const __half2*>(&w3);
#pragma unroll
            for (int q = 0; q < 4; q++) {
                float2 f0 = __half22float2(h0[q]);
                float2 f1 = __half22float2(h1[q]);
                float2 f2 = __half22float2(h2[q]);
                float2 f3 = __half22float2(h3[q]);
                acc[2*q + 0] += (f0.x + f1.x) + (f2.x + f3.x);
                acc[2*q + 1] += (f0.y + f1.y) + (f2.y + f3.y);
            }
        }
        for (; t < cnt; t++) {
            int j = __shfl_sync(0xffffffffu, nidx, t);
            uint4 w = *reinterpret_cast<const uint4*>(g_h2 + (size_t)j * D + lane * 8);
            const __half2* hv = reinterpret_cast<const __half2*>(&w);
#pragma unroll
            for (int q = 0; q < 4; q++) {
                float2 f = __half22float2(hv[q]);
                acc[2*q + 0] += f.x;
                acc[2*q + 1] += f.y;
            }
        }
    }

    float r = g_drs[i];
    float4 v0 = make_float4(acc[0]*r, acc[1]*r, acc[2]*r, acc[3]*r);
    float4 v1 = make_float4(acc[4]*r, acc[5]*r, acc[6]*r, acc[7]*r);
    float* orow = out + (size_t)i * D + lane * 8;
    __stcs(reinterpret_cast<float4*>(orow),     v0);
    __stcs(reinterpret_cast<float4*>(orow + 4), v1);
}

// ---------------------------------------------------------------------------
// Launch: (cvt x,W on s2) || (memset cnt8 -> cnt_edges8 -> drs);
//         GEMM on s2 after drs; (scan1/2/3 + build_col) on main; join -> agg.
// ---------------------------------------------------------------------------
extern "C" void kernel_launch(void* const* d_in, const int* in_sizes, int n_in,
                              void* d_out, int out_size) {
    const float* x  = (const float*)d_in[0];   // [N,256]
    const float* W  = (const float*)d_in[1];   // [256,256]
    const int*   ei = (const int*)d_in[2];     // [2,E]

    int N = in_sizes[0] / D;
    int E = in_sizes[2] / 2;
    const int* src = ei;
    const int* dst = ei + E;
    float* out = (float*)d_out;

    int nbN = (N + 255) / 256;
    int nbE = (E + 255) / 256;

    static cudaStream_t s2 = nullptr;
    static cudaEvent_t evFork = nullptr, evDrs = nullptr, evJoin = nullptr;
    static void* cnt8Ptr = nullptr;
    static __half* xh = nullptr;
    static __half* wh = nullptr;
    if (s2 == nullptr) {
        cudaStreamCreateWithFlags(&s2, cudaStreamNonBlocking);
        cudaEventCreateWithFlags(&evFork, cudaEventDisableTiming);
        cudaEventCreateWithFlags(&evDrs, cudaEventDisableTiming);
        cudaEventCreateWithFlags(&evJoin, cudaEventDisableTiming);
        cudaFuncSetAttribute(hgemm16, cudaFuncAttributeMaxDynamicSharedMemorySize,
                             STAGES * 2 * TILEH * (int)sizeof(__half));
        cudaGetSymbolAddress(&cnt8Ptr, g_cnt8);
        cudaGetSymbolAddress((void**)&xh, g_xh);
        cudaGetSymbolAddress((void**)&wh, g_wh);
    }

    // Fork at entry: conversions run on s2 while main builds the histogram.
    cudaEventRecord(evFork, 0);
    cudaStreamWaitEvent(s2, evFork, 0);
    cvt_f2h<<<(N * 32 + 255) / 256, 256, 0, s2>>>(x, xh, N * 32);
    cvt_f2h<<<(D * 32 + 255) / 256, 256, 0, s2>>>(W, wh, D * 32);

    // Main: 8-way split histogram -> drs (merges buckets) -> event.
    cudaMemsetAsync(cnt8Ptr, 0, (size_t)8 * MAXN * sizeof(int), 0);
    cnt_edges8 <<<nbE, 256>>>(src, E);
    drs_compute<<<nbN, 256>>>(N);
    cudaEventRecord(evDrs, 0);

    // GEMM on s2 (needs xh, wh, drs).
    cudaStreamWaitEvent(s2, evDrs, 0);
    {
        dim3 grid(D / 128, (N + 127) / 128);
        hgemm16<<<grid, 256, STAGES * 2 * TILEH * (int)sizeof(__half), s2>>>(xh, wh, N);
    }
    cudaEventRecord(evJoin, s2);

    // Main: CSR build in parallel with the GEMM.
    scan_phase1<<<nbN, 256>>>(N);
    scan_phase2<<<1,   512>>>(nbN);
    scan_phase3<<<nbN, 256>>>(N, E);
    build_col  <<<nbE, 256>>>(src, dst, E);

    // Join: aggregate needs both h2 and the CSR.
    cudaStreamWaitEvent(0, evJoin, 0);
    aggregate<<<(N + 7) / 8, 256>>>(out, N);
}

// round 17
// speedup vs baseline: 1.0084x; 1.0084x over previous
#include <cuda_runtime.h>
#include <cuda_fp16.h>
#include <cstdint>
#include <cstddef>

// Problem constants: N=100000, D_IN=D_OUT=256, E=3.2M
#define MAXN 100352
#define MAXE 3200000
#define D    256

// Scratch (device globals; allocation is forbidden)
__device__ __align__(16) __half g_h2[(size_t)MAXN * D];  // drs[j] * (x@W^T)[j], fp16
__device__ __align__(16) __half g_xh[(size_t)MAXN * D];  // fp16(x); rows >= N stay zero
__device__ __align__(16) __half g_wh[D * D];             // fp16(W)
__device__ float g_drs[MAXN];
__device__ int   g_cnt8[8 * MAXN];   // 8-way split histogram (contention /8)
__device__ int   g_cnt[MAXN];        // merged degree (written by drs_compute)
__device__ int   g_excl[MAXN];
__device__ int   g_blksum[512];
__device__ int   g_rowptr[MAXN + 1];
__device__ int   g_off[MAXN];
__device__ int   g_col[MAXE];

__device__ __forceinline__ uint32_t smem_u32(const void* p) {
    return (uint32_t)__cvta_generic_to_shared(p);
}

__device__ __forceinline__ void cp_cg16(uint32_t dst, const void* src) {
    asm volatile("cp.async.cg.shared.global [%0], [%1], 16;" :: "r"(dst), "l"(src));
}

template<int NPend>
__device__ __forceinline__ void cp_wait() {
    asm volatile("cp.async.wait_group %0;" :: "n"(NPend) : "memory");
}

// ---------------------------------------------------------------------------
// fp32 -> fp16 bulk convert (8 floats / thread)
// ---------------------------------------------------------------------------
__global__ void cvt_f2h(const float* __restrict__ in, __half* __restrict__ out, int n8) {
    int i = blockIdx.x * blockDim.x + threadIdx.x;
    if (i >= n8) return;
    float4 a = reinterpret_cast<const float4*>(in)[2 * i];
    float4 b = reinterpret_cast<const float4*>(in)[2 * i + 1];
    __half2 h[4];
    h[0] = __floats2half2_rn(a.x, a.y);
    h[1] = __floats2half2_rn(a.z, a.w);
    h[2] = __floats2half2_rn(b.x, b.y);
    h[3] = __floats2half2_rn(b.z, b.w);
    reinterpret_cast<uint4*>(out)[i] = *reinterpret_cast<uint4*>(h);
}

// ---------------------------------------------------------------------------
// Degree histogram, 8-way split: per-address contention drops 32 -> 4.
// ---------------------------------------------------------------------------
__global__ void cnt_edges8(const int* __restrict__ src, int E) {
    int e = blockIdx.x * blockDim.x + threadIdx.x;
    if (e < E) {
        int b = e & 7;
        atomicAdd(&g_cnt8[b * MAXN + src[e]], 1);
    }
}

// drs = rsqrt(deg+1); also writes merged g_cnt for the scan.
__global__ void drs_compute(int N) {
    int i = blockIdx.x * blockDim.x + threadIdx.x;
    if (i < N) {
        int c = 0;
#pragma unroll
        for (int b = 0; b < 8; b++) c += g_cnt8[b * MAXN + i];
        g_cnt[i] = c;
        g_drs[i] = rsqrtf((float)c + 1.0f);
    }
}

// ---------------------------------------------------------------------------
// Prefix sum over g_cnt -> g_rowptr
// ---------------------------------------------------------------------------
__global__ void scan_phase1(int N) {
    __shared__ int sh[256];
    int i = blockIdx.x * 256 + threadIdx.x;
    int v = (i < N) ? g_cnt[i] : 0;
    sh[threadIdx.x] = v;
    __syncthreads();
#pragma unroll
    for (int off = 1; off < 256; off <<= 1) {
        int t = (threadIdx.x >= off) ? sh[threadIdx.x - off] : 0;
        __syncthreads();
        sh[threadIdx.x] += t;
        __syncthreads();
    }
    if (i < N) g_excl[i] = sh[threadIdx.x] - v;
    if (threadIdx.x == 255) g_blksum[blockIdx.x] = sh[255];
}

__global__ void scan_phase2(int nb) {
    __shared__ int sh[512];
    int t = threadIdx.x;
    int v = (t < nb) ? g_blksum[t] : 0;
    sh[t] = v;
    __syncthreads();
#pragma unroll
    for (int off = 1; off < 512; off <<= 1) {
        int u = (t >= off) ? sh[t - off] : 0;
        __syncthreads();
        sh[t] += u;
        __syncthreads();
    }
    if (t < nb) g_blksum[t] = sh[t] - v;
}

__global__ void scan_phase3(int N, int E) {
    int i = blockIdx.x * 256 + threadIdx.x;
    if (i < N) {
        int r = g_excl[i] + g_blksum[blockIdx.x];
        g_rowptr[i] = r;
        g_off[i] = r;
    }
    if (i == 0) g_rowptr[N] = E;
}

__global__ void build_col(const int* __restrict__ src, const int* __restrict__ dst, int E) {
    int e = blockIdx.x * blockDim.x + threadIdx.x;
    if (e < E) {
        int p = atomicAdd(&g_off[src[e]], 1);
        g_col[p] = dst[e];
    }
}

// ---------------------------------------------------------------------------
// cp.async 4-stage (prefetch-3) pipelined HGEMM (fp16 in, fp32 acc):
//   g_h2 = fp16( drs[i] * (xh @ wh^T) )
// 128x128 block tile, BK=32, 8 warps (2x4 layout), 80B smem row stride.
// R7-proven sync skeleton (commit -> wait -> sync -> compute -> sync);
// only the prefetch depth is deepened 2 -> 3 to cover DRAM-tier A loads.
// smem = 4 stages x 20KB = 81.9KB -> still 2 CTAs/SM.
// ---------------------------------------------------------------------------
#define BK      32
#define STRIDE  40
#define TILEH   (128 * STRIDE)
#define STAGES  4

__global__ void __launch_bounds__(256, 2) hgemm16(const __half* __restrict__ Ah,
                                                  const __half* __restrict__ Bh,
                                                  int M) {
    extern __shared__ __half smemraw[];

    const int tid  = threadIdx.x;
    const int lane = tid & 31;
    const int wid  = tid >> 5;
    const int wm   = wid >> 2;
    const int wn   = wid & 3;
    const int brow = blockIdx.y * 128;
    const int bcol = blockIdx.x * 128;

    float acc[4][4][4];
#pragma unroll
    for (int mt = 0; mt < 4; mt++)
#pragma unroll
        for (int nt = 0; nt < 4; nt++)
#pragma unroll
            for (int q = 0; q < 4; q++) acc[mt][nt][q] = 0.0f;

    const int c0r = (tid)       >> 2, c0s = ((tid)       & 3) * 8;
    const int c1r = (tid + 256) >> 2, c1s = ((tid + 256) & 3) * 8;

    auto load_stage = [&](int st, int k0) {
        __half* As = smemraw + st * 2 * TILEH;
        __half* Bs = As + TILEH;
        cp_cg16(smem_u32(As + c0r * STRIDE + c0s), Ah + (size_t)(brow + c0r) * 256 + k0 + c0s);
        cp_cg16(smem_u32(Bs + c0r * STRIDE + c0s), Bh + (size_t)(bcol + c0r) * 256 + k0 + c0s);
        cp_cg16(smem_u32(As + c1r * STRIDE + c1s), Ah + (size_t)(brow + c1r) * 256 + k0 + c1s);
        cp_cg16(smem_u32(Bs + c1r * STRIDE + c1s), Bh + (size_t)(bcol + c1r) * 256 + k0 + c1s);
        asm volatile("cp.async.commit_group;" ::: "memory");
    };

    auto compute_stage = [&](int st) {
        __half* As = smemraw + st * 2 * TILEH;
        __half* Bs = As + TILEH;
#pragma unroll
        for (int ks = 0; ks < 2; ks++) {
            uint32_t a[4][4], b[4][2];
#pragma unroll
            for (int mt = 0; mt < 4; mt++) {
                uint32_t addr = smem_u32(As + (wm * 64 + mt * 16 + (lane & 15)) * STRIDE
                                            + ks * 16 + (lane >> 4) * 8);
                asm volatile("ldmatrix.sync.aligned.m8n8.x4.shared.b16 {%0,%1,%2,%3}, [%4];"
                             : "=r"(a[mt][0]), "=r"(a[mt][1]), "=r"(a[mt][2]), "=r"(a[mt][3])
                             : "r"(addr));
            }
            // B: two x4 loads, each covering an adjacent n-tile pair.
#pragma unroll
            for (int ntp = 0; ntp < 2; ntp++) {
                int row = wn * 32 + ntp * 16 + (lane >> 4) * 8 + (lane & 7);
                int kof = ks * 16 + ((lane >> 3) & 1) * 8;
                uint32_t addr = smem_u32(Bs + row * STRIDE + kof);
                asm volatile("ldmatrix.sync.aligned.m8n8.x4.shared.b16 {%0,%1,%2,%3}, [%4];"
                             : "=r"(b[2*ntp][0]), "=r"(b[2*ntp][1]),
                               "=r"(b[2*ntp+1][0]), "=r"(b[2*ntp+1][1])
                             : "r"(addr));
            }
#pragma unroll
            for (int mt = 0; mt < 4; mt++)
#pragma unroll
                for (int nt = 0; nt < 4; nt++)
                    asm volatile(
                        "mma.sync.aligned.m16n8k16.row.col.f32.f16.f16.f32 "
                        "{%0,%1,%2,%3},{%4,%5,%6,%7},{%8,%9},{%0,%1,%2,%3};"
                        : "+f"(acc[mt][nt][0]), "+f"(acc[mt][nt][1]),
                          "+f"(acc[mt][nt][2]), "+f"(acc[mt][nt][3])
                        : "r"(a[mt][0]), "r"(a[mt][1]), "r"(a[mt][2]), "r"(a[mt][3]),
                          "r"(b[nt][0]), "r"(b[nt][1]));
        }
    };

    // Prologue: fill 3 stages (prefetch depth 3).
    load_stage(0, 0);
    load_stage(1, BK);
    load_stage(2, 2 * BK);

    // Mainloop: commit(it+3) -> wait (group it complete) -> sync -> compute -> sync.
#pragma unroll
    for (int it = 0; it < 8; it++) {
        if (it + 3 < 8) load_stage((it + 3) % STAGES, (it + 3) * BK);
        if (it < 5)       cp_wait<3>();
        else if (it == 5) cp_wait<2>();
        else if (it == 6) cp_wait<1>();
        else              cp_wait<0>();
        __syncthreads();
        compute_stage(it % STAGES);
        __syncthreads();
    }

    const int tg = lane >> 2, tq = lane & 3;
#pragma unroll
    for (int mt = 0; mt < 4; mt++) {
        int r0 = brow + wm * 64 + mt * 16 + tg;
        int r1 = r0 + 8;
        float s0 = (r0 < M) ? g_drs[r0] : 0.f;
        float s1 = (r1 < M) ? g_drs[r1] : 0.f;
#pragma unroll
        for (int nt = 0; nt < 4; nt++) {
            int c = bcol + wn * 32 + nt * 8 + tq * 2;
            if (r0 < M)
                *reinterpret_cast<__half2*>(g_h2 + (size_t)r0 * D + c) =
                    __floats2half2_rn(acc[mt][nt][0] * s0, acc[mt][nt][1] * s0);
            if (r1 < M)
                *reinterpret_cast<__half2*>(g_h2 + (size_t)r1 * D + c) =
                    __floats2half2_rn(acc[mt][nt][2] * s1, acc[mt][nt][3] * s1);
        }
    }
}

// ---------------------------------------------------------------------------
// Aggregation: one warp per node, 4-way unrolled gather (h2 prescaled by drs).
// out[i] = drs[i] * ( h2[i] + sum_{j in adj(i)} h2[j] )
// ---------------------------------------------------------------------------
__global__ void __launch_bounds__(256) aggregate(float* __restrict__ out, int N) {
    int warp = (blockIdx.x * blockDim.x + threadIdx.x) >> 5;
    int lane = threadIdx.x & 31;
    if (warp >= N) return;
    const int i = warp;

    float acc[8];
    {
        uint4 w = *reinterpret_cast<const uint4*>(g_h2 + (size_t)i * D + lane * 8);
        const __half2* hv = reinterpret_cast<const __half2*>(&w);
#pragma unroll
        for (int q = 0; q < 4; q++) {
            float2 f = __half22float2(hv[q]);
            acc[2*q + 0] = f.x;
            acc[2*q + 1] = f.y;
        }
    }

    int s = g_rowptr[i];
    int e = g_rowptr[i + 1];
    for (int b = s; b < e; b += 32) {
        int nidx = (b + lane < e) ? __ldcs(&g_col[b + lane]) : 0;
        int cnt = min(32, e - b);
        int t = 0;
        for (; t + 4 <= cnt; t += 4) {
            int j0 = __shfl_sync(0xffffffffu, nidx, t + 0);
            int j1 = __shfl_sync(0xffffffffu, nidx, t + 1);
            int j2 = __shfl_sync(0xffffffffu, nidx, t + 2);
            int j3 = __shfl_sync(0xffffffffu, nidx, t + 3);
            uint4 w0 = *reinterpret_cast<const uint4*>(g_h2 + (size_t)j0 * D + lane * 8);
            uint4 w1 = *reinterpret_cast<const uint4*>(g_h2 + (size_t)j1 * D + lane * 8);
            uint4 w2 = *reinterpret_cast<const uint4*>(g_h2 + (size_t)j2 * D + lane * 8);
            uint4 w3 = *reinterpret_cast<const uint4*>(g_h2 + (size_t)j3 * D + lane * 8);
            const __half2* h0 = reinterpret_cast<const __half2*>(&w0);
            const __half2* h1 = reinterpret_cast<const __half2*>(&w1);
            const __half2* h2 = reinterpret_cast<const __half2*>(&w2);
            const __half2* h3 = reinterpret_cast<const __half2*>(&w3);
#pragma unroll
            for (int q = 0; q < 4; q++) {
                float2 f0 = __half22float2(h0[q]);
                float2 f1 = __half22float2(h1[q]);
                float2 f2 = __half22float2(h2[q]);
                float2 f3 = __half22float2(h3[q]);
                acc[2*q + 0] += (f0.x + f1.x) + (f2.x + f3.x);
                acc[2*q + 1] += (f0.y + f1.y) + (f2.y + f3.y);
            }
        }
        for (; t < cnt; t++) {
            int j = __shfl_sync(0xffffffffu, nidx, t);
            uint4 w = *reinterpret_cast<const uint4*>(g_h2 + (size_t)j * D + lane * 8);
            const __half2* hv = reinterpret_cast<const __half2*>(&w);
#pragma unroll
            for (int q = 0; q < 4; q++) {
                float2 f = __half22float2(hv[q]);
                acc[2*q + 0] += f.x;
                acc[2*q + 1] += f.y;
            }
        }
    }

    float r = g_drs[i];
    float4 v0 = make_float4(acc[0]*r, acc[1]*r, acc[2]*r, acc[3]*r);
    float4 v1 = make_float4(acc[4]*r, acc[5]*r, acc[6]*r, acc[7]*r);
    float* orow = out + (size_t)i * D + lane * 8;
    __stcs(reinterpret_cast<float4*>(orow),     v0);
    __stcs(reinterpret_cast<float4*>(orow + 4), v1);
}

// ---------------------------------------------------------------------------
// Launch: (cvt x,W on s2) || (memset cnt8 -> cnt_edges8 -> drs);
//         GEMM on s2 after drs; (scan1/2/3 + build_col) on main; join -> agg.
// ---------------------------------------------------------------------------
extern "C" void kernel_launch(void* const* d_in, const int* in_sizes, int n_in,
                              void* d_out, int out_size) {
    const float* x  = (const float*)d_in[0];   // [N,256]
    const float* W  = (const float*)d_in[1];   // [256,256]
    const int*   ei = (const int*)d_in[2];     // [2,E]

    int N = in_sizes[0] / D;
    int E = in_sizes[2] / 2;
    const int* src = ei;
    const int* dst = ei + E;
    float* out = (float*)d_out;

    int nbN = (N + 255) / 256;
    int nbE = (E + 255) / 256;

    static cudaStream_t s2 = nullptr;
    static cudaEvent_t evFork = nullptr, evDrs = nullptr, evJoin = nullptr;
    static void* cnt8Ptr = nullptr;
    static __half* xh = nullptr;
    static __half* wh = nullptr;
    if (s2 == nullptr) {
        cudaStreamCreateWithFlags(&s2, cudaStreamNonBlocking);
        cudaEventCreateWithFlags(&evFork, cudaEventDisableTiming);
        cudaEventCreateWithFlags(&evDrs, cudaEventDisableTiming);
        cudaEventCreateWithFlags(&evJoin, cudaEventDisableTiming);
        cudaFuncSetAttribute(hgemm16, cudaFuncAttributeMaxDynamicSharedMemorySize,
                             STAGES * 2 * TILEH * (int)sizeof(__half));
        cudaGetSymbolAddress(&cnt8Ptr, g_cnt8);
        cudaGetSymbolAddress((void**)&xh, g_xh);
        cudaGetSymbolAddress((void**)&wh, g_wh);
    }

    // Fork at entry: conversions run on s2 while main builds the histogram.
    cudaEventRecord(evFork, 0);
    cudaStreamWaitEvent(s2, evFork, 0);
    cvt_f2h<<<(N * 32 + 255) / 256, 256, 0, s2>>>(x, xh, N * 32);
    cvt_f2h<<<(D * 32 + 255) / 256, 256, 0, s2>>>(W, wh, D * 32);

    // Main: 8-way split histogram -> drs (merges buckets) -> event.
    cudaMemsetAsync(cnt8Ptr, 0, (size_t)8 * MAXN * sizeof(int), 0);
    cnt_edges8 <<<nbE, 256>>>(src, E);
    drs_compute<<<nbN, 256>>>(N);
    cudaEventRecord(evDrs, 0);

    // GEMM on s2 (needs xh, wh, drs).
    cudaStreamWaitEvent(s2, evDrs, 0);
    {
        dim3 grid(D / 128, (N + 127) / 128);
        hgemm16<<<grid, 256, STAGES * 2 * TILEH * (int)sizeof(__half), s2>>>(xh, wh, N);
    }
    cudaEventRecord(evJoin, s2);

    // Main: CSR build in parallel with the GEMM.
    scan_phase1<<<nbN, 256>>>(N);
    scan_phase2<<<1,   512>>>(nbN);
    scan_phase3<<<nbN, 256>>>(N, E);
    build_col  <<<nbE, 256>>>(src, dst, E);

    // Join: aggregate needs both h2 and the CSR.
    cudaStreamWaitEvent(0, evJoin, 0);
    aggregate<<<(N + 7) / 8, 256>>>(out, N);
}